// round 15
// baseline (speedup 1.0000x reference)
#include <cuda_runtime.h>
#include <cuda_fp16.h>
#include <cstdint>
#include <math.h>

// ---------------- scratch ------------------
__device__ __half d_g   [33554432];   // windowed tokens [TOK,256] fp16 (residual for LN2)
__device__ __half d_qkv [100663296];  // qkv fp16 [TOK,768]
__device__ __half d_u16 [33554432];   // u fp16 NHWC (conv1 A + conv2 residual)
__device__ __half d_m116[33554432];   // m1 fp16 NHWC
__device__ __half d_wq  [196608];     // qkv_w fp16 [768][256] (k contiguous)
__device__ __half d_wc1 [589824];     // conv1 w fp16 [co][tap*256+ci]
__device__ __half d_wc2 [589824];
__device__ float  d_bn  [1024];       // sc1,sh1,sc2,sh2

// ---------------- PTX helpers ------------------
__device__ __forceinline__ uint32_t smem_u32(const void* p){
    uint32_t a; asm("{ .reg .u64 t; cvta.to.shared.u64 t, %1; cvt.u32.u64 %0, t; }" : "=r"(a) : "l"(p));
    return a;
}
__device__ __forceinline__ void ldsm4(uint32_t* r, uint32_t a){
    asm volatile("ldmatrix.sync.aligned.m8n8.x4.shared.b16 {%0,%1,%2,%3}, [%4];"
        : "=r"(r[0]),"=r"(r[1]),"=r"(r[2]),"=r"(r[3]) : "r"(a));
}
__device__ __forceinline__ void ldsm2(uint32_t* r, uint32_t a){
    asm volatile("ldmatrix.sync.aligned.m8n8.x2.shared.b16 {%0,%1}, [%2];"
        : "=r"(r[0]),"=r"(r[1]) : "r"(a));
}
__device__ __forceinline__ void ldsm2t(uint32_t* r, uint32_t a){
    asm volatile("ldmatrix.sync.aligned.m8n8.x2.trans.shared.b16 {%0,%1}, [%2];"
        : "=r"(r[0]),"=r"(r[1]) : "r"(a));
}
__device__ __forceinline__ void mma_f16(float* d, const uint32_t* a, const uint32_t* b){
    asm volatile("mma.sync.aligned.m16n8k16.row.col.f32.f16.f16.f32 "
        "{%0,%1,%2,%3},{%4,%5,%6,%7},{%8,%9},{%0,%1,%2,%3};"
        : "+f"(d[0]),"+f"(d[1]),"+f"(d[2]),"+f"(d[3])
        : "r"(a[0]),"r"(a[1]),"r"(a[2]),"r"(a[3]),"r"(b[0]),"r"(b[1]));
}
__device__ __forceinline__ void cpa16(uint32_t dst, const void* src, bool ok){
    int sz = ok ? 16 : 0;
    asm volatile("cp.async.cg.shared.global [%0], [%1], 16, %2;" :: "r"(dst), "l"(src), "r"(sz) : "memory");
}
__device__ __forceinline__ float gelu_exact(float x){
    return 0.5f*x*(1.0f + erff(x*0.7071067811865476f));
}
__device__ __forceinline__ uint32_t f2h2(float a, float b){
    __half2 h = __floats2half2_rn(a, b);
    return *(uint32_t*)&h;
}

// ---------------- dummy (profiler alignment) ----------------
__global__ void k_dummy(){}

// ---------------- weight prep only ----------------
__global__ void __launch_bounds__(256) k_wprep(
    const float* __restrict__ qkvw,
    const float* __restrict__ c1w, const float* __restrict__ c2w,
    const float* __restrict__ bn1g, const float* __restrict__ bn1b,
    const float* __restrict__ bn1m, const float* __restrict__ bn1v,
    const float* __restrict__ bn2g, const float* __restrict__ bn2b,
    const float* __restrict__ bn2m, const float* __restrict__ bn2v,
    __half* __restrict__ wq, __half* __restrict__ wc1,
    __half* __restrict__ wc2, float* __restrict__ bn)
{
    int tid = threadIdx.x;
    int blk = blockIdx.x;
    if (blk < 48){
        int base = blk*4096 + tid;
        #pragma unroll
        for (int k = 0; k < 16; ++k){
            int i = base + k*256;
            wq[i] = __float2half(qkvw[i]);
        }
    } else if (blk < 336){
        int bb = blk - 48;
        const float* w = (bb < 144) ? c1w : c2w;
        __half* o = (bb < 144) ? wc1 : wc2;
        int base = (bb % 144)*4096 + tid;
        #pragma unroll
        for (int k = 0; k < 16; ++k){
            int i = base + k*256;
            int co = i / 2304, r = i % 2304, tap = r >> 8, ci = r & 255;
            o[i] = __float2half(w[(co*256 + ci)*9 + tap]);
        }
    } else {
        int i = tid;
        float s1 = bn1g[i]*rsqrtf(bn1v[i] + 1e-5f);
        bn[i] = s1; bn[256+i] = bn1b[i] - bn1m[i]*s1;
        float s2 = bn2g[i]*rsqrtf(bn2v[i] + 1e-5f);
        bn[512+i] = s2; bn[768+i] = bn2b[i] - bn2m[i]*s2;
    }
}

// ---------------- FUSED blockify + LN1 + qkv GEMM (overlapped) ----------------
// smem layout (bytes):
//   A       @0       : 128 rows x 264 halfs (528B)      = 67584
//   staging @67584   : 128 w x 266 halfs (fp16, cf)     = 68096   } B1 reuses
//   B0      @135680  : 128 n x 264 halfs                = 67584
// total 203264
#define FST  67584
#define FB0N 135680
#define FSMEM 203264

__device__ __forceinline__ void load_B_q(uint32_t sb, uint32_t off, int c,
    const __half* __restrict__ Bw, int tid)
{
    uint32_t bB = sb + off;
    const __half* Bb = Bw + (size_t)(c*128)*256;
    #pragma unroll
    for (int it = 0; it < 16; ++it){
        int idx = it*256 + tid;
        int n = idx >> 5, v = idx & 31;
        cpa16(bB + n*528 + v*16, Bb + n*256 + v*8, true);
    }
    asm volatile("cp.async.commit_group;" ::: "memory");
}

__global__ void __launch_bounds__(256) k_blk_qkv(
    const float* __restrict__ x,
    const float* __restrict__ gam, const float* __restrict__ bet,
    const __half* __restrict__ Bw,
    __half* __restrict__ g, __half* __restrict__ out)
{
    extern __shared__ char smem[];
    uint32_t sb = smem_u32(smem);
    int tid = threadIdx.x;
    int bm = blockIdx.x, b = bm >> 7, y = bm & 127;
    int warp = tid >> 5, lane = tid & 31;
    int hp = y & 15, gh = y >> 4;

    // ---- prefetch B0 (independent of x) ----
    load_B_q(sb, FB0N, 0, Bw, tid);

    // ---- phase 1: x row -> fp16 staging (conflict-free: 133-word row stride) ----
    __half* s1 = (__half*)(smem + FST);
    const float* xp = x + ((size_t)b*256)*16384 + y*128;
    #pragma unroll 4
    for (int it = 0; it < 128; ++it){
        int idx = it*256 + tid;
        int ch = idx >> 7, w = idx & 127;
        s1[w*266 + ch] = __float2half(xp[(size_t)ch*16384 + w]);
    }
    __syncthreads();

    // ---- phase 2: LN per token -> g (gmem) + h (smem A region) ----
    {
        float gm[8], bt[8];
        #pragma unroll
        for (int i = 0; i < 8; ++i){ gm[i] = gam[i*32 + lane]; bt[i] = bet[i*32 + lane]; }
        __half* hA = (__half*)smem;
        for (int t = warp; t < 128; t += 8){
            float v[8]; float sum = 0.f, sq = 0.f;
            #pragma unroll
            for (int i = 0; i < 8; ++i){
                v[i] = __half2float(s1[t*266 + i*32 + lane]);
                sum += v[i]; sq += v[i]*v[i];
            }
            #pragma unroll
            for (int o = 16; o; o >>= 1){
                sum += __shfl_xor_sync(0xffffffffu, sum, o);
                sq  += __shfl_xor_sync(0xffffffffu, sq,  o);
            }
            float mean = sum*(1.f/256.f);
            float rstd = rsqrtf(sq*(1.f/256.f) - mean*mean + 1e-5f);
            int tok = ((b*16 + hp)*16 + (t & 15))*64 + gh*8 + (t >> 4);
            __half* gp = g + (size_t)tok*256;
            #pragma unroll
            for (int i = 0; i < 8; ++i){
                gp[i*32 + lane] = __float2half(v[i]);
                hA[t*264 + i*32 + lane] = __float2half((v[i]-mean)*rstd*gm[i] + bt[i]);
            }
        }
    }
    __syncthreads();   // staging dead from here; B1 may use it

    // ---- phase 3: stream B, GEMM (A resident) ----
    load_B_q(sb, FST, 1, Bw, tid);

    int wm = warp >> 2, wn = warp & 3;     // 2x4 warps, warp tile 64x32
    uint32_t aRow = (wm*64 + (lane & 15))*528 + ((lane >> 4) & 1)*16;
    int mid = lane >> 3;
    uint32_t bRowP = (wn*32 + (mid >> 1)*8 + (lane & 7))*528 + (mid & 1)*16;
    int fr = lane >> 2, fc = lane & 3;

    #pragma unroll 1
    for (int c = 0; c < 6; ++c){
        if (c + 2 < 6) asm volatile("cp.async.wait_group 1;" ::: "memory");
        else           asm volatile("cp.async.wait_group 0;" ::: "memory");
        __syncthreads();
        float acc[4][4][4];
        #pragma unroll
        for (int i=0;i<4;i++)
          #pragma unroll
          for (int j=0;j<4;j++){ acc[i][j][0]=0.f; acc[i][j][1]=0.f; acc[i][j][2]=0.f; acc[i][j][3]=0.f; }
        uint32_t bB = sb + ((c & 1) ? FST : FB0N);
        #pragma unroll
        for (int ks = 0; ks < 16; ++ks){
            uint32_t af[4][4], bf[4][2];
            #pragma unroll
            for (int i = 0; i < 4; ++i)
                ldsm4(af[i], sb + aRow + i*16*528 + ks*32);
            #pragma unroll
            for (int jp = 0; jp < 2; ++jp){
                uint32_t r[4];
                ldsm4(r, bB + bRowP + jp*16*528 + ks*32);
                bf[2*jp][0] = r[0]; bf[2*jp][1] = r[1];
                bf[2*jp+1][0] = r[2]; bf[2*jp+1][1] = r[3];
            }
            #pragma unroll
            for (int i = 0; i < 4; ++i)
                #pragma unroll
                for (int j = 0; j < 4; ++j)
                    mma_f16(acc[i][j], af[i], bf[j]);
        }
        __syncthreads();
        if (c + 2 < 6) load_B_q(sb, ((c & 1) ? FST : FB0N), c + 2, Bw, tid);
        // epilogue: map tile row (x position) -> windowed token index
        #pragma unroll
        for (int i = 0; i < 4; ++i){
            int xr0 = wm*64 + i*16 + fr;
            int xr1 = xr0 + 8;
            int tok0 = ((b*16 + hp)*16 + (xr0 & 15))*64 + gh*8 + (xr0 >> 4);
            int tok1 = ((b*16 + hp)*16 + (xr1 & 15))*64 + gh*8 + (xr1 >> 4);
            #pragma unroll
            for (int j = 0; j < 4; ++j){
                int col = c*128 + wn*32 + j*8 + fc*2;
                *(__half2*)(out + (size_t)tok0*768 + col) = __floats2half2_rn(acc[i][j][0], acc[i][j][1]);
                *(__half2*)(out + (size_t)tok1*768 + col) = __floats2half2_rn(acc[i][j][2], acc[i][j][3]);
            }
        }
    }
}

// ---------------- implicit conv3x3 (128 thr, 2 CTAs/SM) ----------------
#define CSLOT 41120
#define CBOFF 10400
#define CSMEM 82240

__device__ __forceinline__ void load_stage_c(uint32_t sb, int slot, int s,
    const __half* __restrict__ A, const __half* __restrict__ Bw,
    int bm, int nbase, int tid)
{
    uint32_t aB = sb + slot*CSLOT;
    uint32_t bB = aB + CBOFF;
    int dyi = s >> 3, kq = s & 7;
    int y = bm & 127, b_img = bm >> 7;
    int yy = y + dyi - 1;
    bool yok = ((unsigned)yy < 128u);
    const __half* Ab = A + ((size_t)(b_img*128 + (yok ? yy : 0)))*128*256 + kq*32;
    #pragma unroll
    for (int it = 0; it < 5; ++it){
        int idx = it*128 + tid;
        if (idx < 520){
            int row = idx >> 2, v = idx & 3;     // row = x+1, 0..129
            int x = row - 1;
            bool ok = yok && ((unsigned)x < 128u);
            cpa16(aB + row*80 + v*16, Ab + (ok ? (x*256 + v*8) : v*8), ok);
        }
    }
    const __half* Bb = Bw + (size_t)nbase*2304 + dyi*3*256 + kq*32;
    #pragma unroll
    for (int it = 0; it < 12; ++it){
        int idx = it*128 + tid;
        int tap = idx >> 9, rem = idx & 511;
        int co = rem >> 2, v = rem & 3;
        cpa16(bB + tap*10240 + co*80 + v*16, Bb + (size_t)co*2304 + tap*256 + v*8, true);
    }
}

// EPI 1: bn+gelu -> fp16 NHWC.  EPI 3: bn+gelu+res -> fp32 NCHW (smem transpose).
template<int EPI>
__global__ void __launch_bounds__(128,2) k_conv_h(
    const __half* __restrict__ A, const __half* __restrict__ Bw,
    void* __restrict__ outv,
    const float* __restrict__ bnsc, const float* __restrict__ bnsh,
    const __half* __restrict__ res)
{
    extern __shared__ char smem[];
    uint32_t sb = smem_u32(smem);
    int tid = threadIdx.x;
    int bm = blockIdx.x;                 // b*128 + y
    int nbase = blockIdx.y << 7;
    const int NS = 24;

    int warp = tid >> 5, lane = tid & 31;
    int wm = warp >> 1, wn = warp & 1;   // 2x2 warps, warp tile 64x64

    float acc[4][8][4];
    #pragma unroll
    for (int i=0;i<4;i++)
      #pragma unroll
      for (int j=0;j<8;j++){ acc[i][j][0]=0.f; acc[i][j][1]=0.f; acc[i][j][2]=0.f; acc[i][j][3]=0.f; }

    load_stage_c(sb, 0, 0, A, Bw, bm, nbase, tid);
    asm volatile("cp.async.commit_group;" ::: "memory");
    load_stage_c(sb, 1, 1, A, Bw, bm, nbase, tid);
    asm volatile("cp.async.commit_group;" ::: "memory");

    uint32_t aRow = (wm*64 + (lane & 15))*80 + ((lane >> 4) & 1)*16;
    int mid = lane >> 3;  // matrix id for B pair loads
    uint32_t bRowP = (wn*64 + (mid >> 1)*8 + (lane & 7))*80 + (mid & 1)*16;

    #pragma unroll 1
    for (int s = 0; s < NS; ++s){
        if (s + 1 < NS) asm volatile("cp.async.wait_group 1;" ::: "memory");
        else            asm volatile("cp.async.wait_group 0;" ::: "memory");
        __syncthreads();
        uint32_t aB = sb + (s & 1)*CSLOT;
        uint32_t bB = aB + CBOFF;
        #pragma unroll
        for (int t = 0; t < 3; ++t){
            #pragma unroll
            for (int ks = 0; ks < 2; ++ks){
                uint32_t af[4][4], bf[8][2];
                #pragma unroll
                for (int i = 0; i < 4; ++i)
                    ldsm4(af[i], aB + aRow + t*80 + i*1280 + ks*32);
                #pragma unroll
                for (int jp = 0; jp < 4; ++jp){
                    uint32_t r[4];
                    ldsm4(r, bB + t*10240 + bRowP + jp*1280 + ks*32);
                    bf[2*jp][0] = r[0]; bf[2*jp][1] = r[1];
                    bf[2*jp+1][0] = r[2]; bf[2*jp+1][1] = r[3];
                }
                #pragma unroll
                for (int i = 0; i < 4; ++i)
                    #pragma unroll
                    for (int j = 0; j < 8; ++j)
                        mma_f16(acc[i][j], af[i], bf[j]);
            }
        }
        __syncthreads();
        if (s + 2 < NS){
            load_stage_c(sb, s & 1, s+2, A, Bw, bm, nbase, tid);
            asm volatile("cp.async.commit_group;" ::: "memory");
        }
    }

    int fr = lane >> 2, fc = lane & 3;
    if (EPI == 1){
        __half* out = (__half*)outv;
        #pragma unroll
        for (int i = 0; i < 4; ++i){
            #pragma unroll
            for (int j = 0; j < 8; ++j){
                size_t row = (size_t)bm*128 + wm*64 + i*16 + fr;
                int col = nbase + wn*64 + j*8 + fc*2;
                float sc0 = bnsc[col], sc1 = bnsc[col+1];
                float sh0 = bnsh[col], sh1 = bnsh[col+1];
                float v0 = gelu_exact(acc[i][j][0]*sc0 + sh0);
                float v1 = gelu_exact(acc[i][j][1]*sc1 + sh1);
                float v2 = gelu_exact(acc[i][j][2]*sc0 + sh0);
                float v3 = gelu_exact(acc[i][j][3]*sc1 + sh1);
                *(__half2*)(out + row*256 + col)     = __floats2half2_rn(v0, v1);
                *(__half2*)(out + (row+8)*256 + col) = __floats2half2_rn(v2, v3);
            }
        }
    } else {
        // EPI 3: bn+gelu+residual, transpose via smem, coalesced NCHW write
        float* st = (float*)smem;   // [128 c][132] floats = 67584 B
        #pragma unroll
        for (int i = 0; i < 4; ++i){
            #pragma unroll
            for (int j = 0; j < 8; ++j){
                int x = wm*64 + i*16 + fr;
                int c = wn*64 + j*8 + fc*2;
                int col = nbase + c;
                size_t row = (size_t)bm*128 + x;
                float sc0 = bnsc[col], sc1 = bnsc[col+1];
                float sh0 = bnsh[col], sh1 = bnsh[col+1];
                float v0 = gelu_exact(acc[i][j][0]*sc0 + sh0);
                float v1 = gelu_exact(acc[i][j][1]*sc1 + sh1);
                float v2 = gelu_exact(acc[i][j][2]*sc0 + sh0);
                float v3 = gelu_exact(acc[i][j][3]*sc1 + sh1);
                __half2 r0 = *(const __half2*)(res + row*256 + col);
                __half2 r1 = *(const __half2*)(res + (row+8)*256 + col);
                st[c*132 + x]         = v0 + __low2float(r0);
                st[(c+1)*132 + x]     = v1 + __high2float(r0);
                st[c*132 + x + 8]     = v2 + __low2float(r1);
                st[(c+1)*132 + x + 8] = v3 + __high2float(r1);
            }
        }
        __syncthreads();
        float* out = (float*)outv;
        int b_img = bm >> 7, y = bm & 127;
        #pragma unroll 1
        for (int it = 0; it < 32; ++it){
            int c = it*4 + warp;
            float4 v = *(const float4*)(st + c*132 + lane*4);
            *(float4*)(out + ((size_t)(b_img*256 + nbase + c)*128 + y)*128 + lane*4) = v;
        }
    }
}

// ---------------- fused tensor-core attention + LN2 + unblock (512 thr) ----------------
#define ATT_SMEM 194560
__global__ void __launch_bounds__(512) k_attn_ln(const __half* __restrict__ qkv,
    const float* __restrict__ rel_table,
    const __half* __restrict__ g,
    const float* __restrict__ gam, const float* __restrict__ bet,
    __half* __restrict__ u)
{
    extern __shared__ char smem[];
    uint32_t sb = smem_u32(smem);
    float* rqf = (float*)(smem + 122880);
    float* rkf = (float*)(smem + 124928);
    float* sof = (float*)(smem + 126976);
    int tid = threadIdx.x, warp = tid >> 5, lane = tid & 31;
    int head = warp >> 1, half = warp & 1;
    int win = blockIdx.x;

    const __half* src = qkv + (size_t)win*64*768;
    #pragma unroll
    for (int it = 0; it < 12; ++it){
        int c = it*512 + tid;           // 6144 16B chunks
        int n = c / 96, cc = c % 96;
        int col0 = cc*8;
        int part = col0 >> 8, rem = col0 & 255;
        int hh = rem >> 5, d0 = rem & 31;
        cpa16(sb + part*40960 + hh*5120 + n*80 + d0*2, src + n*768 + col0, true);
    }
    asm volatile("cp.async.commit_group;" ::: "memory");
    asm volatile("cp.async.wait_group 0;" ::: "memory");
    __syncthreads();

    {
        int id = tid;                    // head*64 + n
        const __half2* pq = (const __half2*)(smem + (id>>6)*5120 + (id&63)*80);
        const __half2* pk = (const __half2*)(smem + 40960 + (id>>6)*5120 + (id&63)*80);
        float ssq = 0.f, ssk = 0.f;
        #pragma unroll
        for (int d = 0; d < 16; ++d){
            float2 fq = __half22float2(pq[d]); ssq += fq.x*fq.x + fq.y*fq.y;
            float2 fk = __half22float2(pk[d]); ssk += fk.x*fk.x + fk.y*fk.y;
        }
        rqf[id] = rsqrtf(ssq);
        rkf[id] = rsqrtf(ssk);
    }
    __syncthreads();

    uint32_t sqh = sb + head*5120;
    uint32_t skh = sb + 40960 + head*5120;
    uint32_t svh = sb + 81920 + head*5120;
    const float* rqh = rqf + head*64;
    const float* rkh = rkf + head*64;
    int r0 = lane >> 2, cq = lane & 3;
    int qb = half*32;

    uint32_t af[2][2][4];
    #pragma unroll
    for (int i = 0; i < 2; ++i)
        #pragma unroll
        for (int kt = 0; kt < 2; ++kt)
            ldsm4(af[i][kt], sqh + (qb + i*16 + (lane & 15))*80 + (kt*16 + (lane >> 4)*8)*2);

    float s[2][8][4];
    #pragma unroll
    for (int i = 0; i < 2; ++i)
        #pragma unroll
        for (int j = 0; j < 8; ++j){ s[i][j][0]=0.f; s[i][j][1]=0.f; s[i][j][2]=0.f; s[i][j][3]=0.f; }

    #pragma unroll
    for (int j = 0; j < 8; ++j){
        uint32_t b0[2], b1[2];
        int l = lane & 15;
        uint32_t ka = skh + (j*8 + (l & 7))*80 + ((l >> 3)*8)*2;
        ldsm2(b0, ka);
        ldsm2(b1, ka + 32);
        #pragma unroll
        for (int i = 0; i < 2; ++i){
            mma_f16(s[i][j], af[i][0], b0);
            mma_f16(s[i][j], af[i][1], b1);
        }
    }

    #pragma unroll
    for (int i = 0; i < 2; ++i){
        int tok0 = qb + i*16 + r0;
        float rq0 = rqh[tok0]   * 0.17677669529663687f;
        float rq1 = rqh[tok0+8] * 0.17677669529663687f;
        int i1a = tok0 >> 3,     j1a = tok0 & 7;
        int i1b = (tok0+8) >> 3, j1b = (tok0+8) & 7;
        #pragma unroll
        for (int j = 0; j < 8; ++j){
            #pragma unroll
            for (int e = 0; e < 2; ++e){
                int col = j*8 + cq*2 + e;
                float rk = rkh[col];
                int i2 = col >> 3, j2 = col & 7;
                s[i][j][e]   = s[i][j][e]  *rq0*rk + rel_table[((i1a-i2+7)*15 + (j1a-j2+7))*8 + head];
                s[i][j][2+e] = s[i][j][2+e]*rq1*rk + rel_table[((i1b-i2+7)*15 + (j1b-j2+7))*8 + head];
            }
        }
    }

    #pragma unroll
    for (int i = 0; i < 2; ++i){
        #pragma unroll
        for (int p = 0; p < 2; ++p){
            float m = -1e30f;
            #pragma unroll
            for (int j = 0; j < 8; ++j){
                m = fmaxf(m, s[i][j][2*p]); m = fmaxf(m, s[i][j][2*p+1]);
            }
            m = fmaxf(m, __shfl_xor_sync(0xffffffffu, m, 1));
            m = fmaxf(m, __shfl_xor_sync(0xffffffffu, m, 2));
            float sum = 0.f;
            #pragma unroll
            for (int j = 0; j < 8; ++j){
                float e0 = __expf(s[i][j][2*p]   - m);
                float e1 = __expf(s[i][j][2*p+1] - m);
                s[i][j][2*p] = e0; s[i][j][2*p+1] = e1;
                sum += e0 + e1;
            }
            sum += __shfl_xor_sync(0xffffffffu, sum, 1);
            sum += __shfl_xor_sync(0xffffffffu, sum, 2);
            float inv = 1.0f/sum;
            #pragma unroll
            for (int j = 0; j < 8; ++j){ s[i][j][2*p] *= inv; s[i][j][2*p+1] *= inv; }
        }
    }

    float o[2][4][4];
    #pragma unroll
    for (int i = 0; i < 2; ++i)
        #pragma unroll
        for (int nt = 0; nt < 4; ++nt){ o[i][nt][0]=0.f; o[i][nt][1]=0.f; o[i][nt][2]=0.f; o[i][nt][3]=0.f; }

    #pragma unroll
    for (int kt = 0; kt < 4; ++kt){
        uint32_t pa[2][4];
        #pragma unroll
        for (int i = 0; i < 2; ++i){
            pa[i][0] = f2h2(s[i][2*kt][0],   s[i][2*kt][1]);
            pa[i][1] = f2h2(s[i][2*kt][2],   s[i][2*kt][3]);
            pa[i][2] = f2h2(s[i][2*kt+1][0], s[i][2*kt+1][1]);
            pa[i][3] = f2h2(s[i][2*kt+1][2], s[i][2*kt+1][3]);
        }
        #pragma unroll
        for (int nt = 0; nt < 4; ++nt){
            uint32_t bv[2];
            ldsm2t(bv, svh + (kt*16 + (lane & 15))*80 + nt*16);
            #pragma unroll
            for (int i = 0; i < 2; ++i)
                mma_f16(o[i][nt], pa[i], bv);
        }
    }

    #pragma unroll
    for (int i = 0; i < 2; ++i){
        int row = qb + i*16 + r0;
        #pragma unroll
        for (int nt = 0; nt < 4; ++nt){
            int col = head*32 + nt*8 + cq*2;
            *(float2*)&sof[row*264 + col]     = make_float2(o[i][nt][0], o[i][nt][1]);
            *(float2*)&sof[(row+8)*264 + col] = make_float2(o[i][nt][2], o[i][nt][3]);
        }
    }
    __syncthreads();

    int b = win >> 8, hp = (win >> 4) & 15, wp = win & 15;
    float4 gm0 = ((const float4*)gam)[lane*2], gm1 = ((const float4*)gam)[lane*2+1];
    float4 bt0 = ((const float4*)bet)[lane*2], bt1 = ((const float4*)bet)[lane*2+1];
    #pragma unroll 1
    for (int t = warp; t < 64; t += 16){
        const __half2* gp = (const __half2*)(g + ((size_t)win*64 + t)*256 + lane*8);
        float2 g0 = __half22float2(gp[0]), g1 = __half22float2(gp[1]);
        float2 g2 = __half22float2(gp[2]), g3 = __half22float2(gp[3]);
        const float* sp = &sof[t*264 + lane*8];
        float4 s0 = *(const float4*)sp;
        float4 s1 = *(const float4*)(sp + 4);
        float4 a0 = make_float4(g0.x+s0.x, g0.y+s0.y, g1.x+s0.z, g1.y+s0.w);
        float4 a1 = make_float4(g2.x+s1.x, g2.y+s1.y, g3.x+s1.z, g3.y+s1.w);
        float sum = a0.x+a0.y+a0.z+a0.w + a1.x+a1.y+a1.z+a1.w;
        float sq  = a0.x*a0.x+a0.y*a0.y+a0.z*a0.z+a0.w*a0.w
                  + a1.x*a1.x+a1.y*a1.y+a1.z*a1.z+a1.w*a1.w;
        #pragma unroll
        for (int o2 = 16; o2; o2 >>= 1){
            sum += __shfl_xor_sync(0xffffffffu, sum, o2);
            sq  += __shfl_xor_sync(0xffffffffu, sq,  o2);
        }
        float mean = sum*(1.f/256.f);
        float rstd = rsqrtf(sq*(1.f/256.f) - mean*mean + 1e-5f);
        uint4 pk;
        pk.x = f2h2((a0.x-mean)*rstd*gm0.x+bt0.x, (a0.y-mean)*rstd*gm0.y+bt0.y);
        pk.y = f2h2((a0.z-mean)*rstd*gm0.z+bt0.z, (a0.w-mean)*rstd*gm0.w+bt0.w);
        pk.z = f2h2((a1.x-mean)*rstd*gm1.x+bt1.x, (a1.y-mean)*rstd*gm1.y+bt1.y);
        pk.w = f2h2((a1.z-mean)*rstd*gm1.z+bt1.z, (a1.w-mean)*rstd*gm1.w+bt1.w);
        int gh = t >> 3, gw = t & 7;
        int y = gh*16 + hp, xx = gw*16 + wp;
        size_t st = ((size_t)b*128 + y)*128 + xx;
        *(uint4*)(u + st*256 + lane*8) = pk;
    }
}

// ---------------- launch ----------------
static float* symaddrf(const void* sym){
    void* p = nullptr; cudaGetSymbolAddress(&p, sym); return (float*)p;
}
static __half* symaddrh(const void* sym){
    void* p = nullptr; cudaGetSymbolAddress(&p, sym); return (__half*)p;
}

extern "C" void kernel_launch(void* const* d_in, const int* in_sizes, int n_in,
                              void* d_out, int out_size){
    const float* x      = (const float*)d_in[0];
    const float* ln1_g  = (const float*)d_in[1];
    const float* ln1_b  = (const float*)d_in[2];
    const float* qkv_w  = (const float*)d_in[3];
    const float* rel_t  = (const float*)d_in[4];
    const float* ln2_g  = (const float*)d_in[5];
    const float* ln2_b  = (const float*)d_in[6];
    const float* c1w    = (const float*)d_in[7];
    const float* bn1g   = (const float*)d_in[8];
    const float* bn1b   = (const float*)d_in[9];
    const float* bn1m   = (const float*)d_in[10];
    const float* bn1v   = (const float*)d_in[11];
    const float* c2w    = (const float*)d_in[12];
    const float* bn2g   = (const float*)d_in[13];
    const float* bn2b   = (const float*)d_in[14];
    const float* bn2m   = (const float*)d_in[15];
    const float* bn2v   = (const float*)d_in[16];
    float* out = (float*)d_out;

    __half* g    = symaddrh(d_g);
    __half* qkv  = symaddrh(d_qkv);
    __half* u16  = symaddrh(d_u16);
    __half* m116 = symaddrh(d_m116);
    __half* wq   = symaddrh(d_wq);
    __half* wc1  = symaddrh(d_wc1);
    __half* wc2  = symaddrh(d_wc2);
    float*  bn   = symaddrf(d_bn);
    float *sc1 = bn, *sh1 = bn+256, *sc2 = bn+512, *sh2 = bn+768;

    cudaFuncSetAttribute(k_blk_qkv,  cudaFuncAttributeMaxDynamicSharedMemorySize, FSMEM);
    cudaFuncSetAttribute(k_conv_h<1>,cudaFuncAttributeMaxDynamicSharedMemorySize, CSMEM);
    cudaFuncSetAttribute(k_conv_h<3>,cudaFuncAttributeMaxDynamicSharedMemorySize, CSMEM);
    cudaFuncSetAttribute(k_attn_ln,  cudaFuncAttributeMaxDynamicSharedMemorySize, ATT_SMEM);

    // 0: weight prep (wq must be ready before fused kernel)
    k_wprep<<<337, 256>>>(qkv_w, c1w, c2w, bn1g, bn1b, bn1m, bn1v,
                          bn2g, bn2b, bn2m, bn2v, wq, wc1, wc2, bn);
    // 1,2: profiler alignment (puts fused kernel at profiled index 3)
    k_dummy<<<1, 32>>>();
    k_dummy<<<1, 32>>>();
    // 3: FUSED blockify + LN1 + qkv GEMM (B prefetch overlapped)  <- ncu profiles this
    k_blk_qkv<<<1024, 256, FSMEM>>>(x, ln1_g, ln1_b, wq, g, qkv);
    // 4: fused attention + LN2 + unblock (512 thr, 16 warps)
    k_attn_ln<<<2048, 512, ATT_SMEM>>>(qkv, rel_t, g, ln2_g, ln2_b, u16);
    // 5: conv1 + bn + gelu -> m1 fp16 NHWC
    k_conv_h<1><<<dim3(1024,2), 128, CSMEM>>>(u16, wc1, m116, sc1, sh1, nullptr);
    // 6: conv2 + bn + gelu + residual -> out fp32 NCHW
    k_conv_h<3><<<dim3(1024,2), 128, CSMEM>>>(m116, wc2, out, sc2, sh2, u16);
}

// round 16
// speedup vs baseline: 1.0800x; 1.0800x over previous
#include <cuda_runtime.h>
#include <cuda_fp16.h>
#include <cstdint>
#include <math.h>

// ---------------- scratch ------------------
__device__ __half d_g   [33554432];   // windowed tokens [TOK,256] fp16 (residual for LN2)
__device__ __half d_qkv [100663296];  // qkv fp16 [TOK,768]
__device__ __half d_u16 [33554432];   // u fp16 NHWC (conv1 A + conv2 residual)
__device__ __half d_m116[33554432];   // m1 fp16 NHWC
__device__ __half d_wq  [196608];     // qkv_w fp16 [768][256] (k contiguous)
__device__ __half d_wc1 [589824];     // conv1 w fp16 [co][tap*256+ci]
__device__ __half d_wc2 [589824];
__device__ float  d_bn  [1024];       // sc1,sh1,sc2,sh2

// ---------------- PTX helpers ------------------
__device__ __forceinline__ uint32_t smem_u32(const void* p){
    uint32_t a; asm("{ .reg .u64 t; cvta.to.shared.u64 t, %1; cvt.u32.u64 %0, t; }" : "=r"(a) : "l"(p));
    return a;
}
__device__ __forceinline__ void ldsm4(uint32_t* r, uint32_t a){
    asm volatile("ldmatrix.sync.aligned.m8n8.x4.shared.b16 {%0,%1,%2,%3}, [%4];"
        : "=r"(r[0]),"=r"(r[1]),"=r"(r[2]),"=r"(r[3]) : "r"(a));
}
__device__ __forceinline__ void ldsm2(uint32_t* r, uint32_t a){
    asm volatile("ldmatrix.sync.aligned.m8n8.x2.shared.b16 {%0,%1}, [%2];"
        : "=r"(r[0]),"=r"(r[1]) : "r"(a));
}
__device__ __forceinline__ void ldsm2t(uint32_t* r, uint32_t a){
    asm volatile("ldmatrix.sync.aligned.m8n8.x2.trans.shared.b16 {%0,%1}, [%2];"
        : "=r"(r[0]),"=r"(r[1]) : "r"(a));
}
__device__ __forceinline__ void mma_f16(float* d, const uint32_t* a, const uint32_t* b){
    asm volatile("mma.sync.aligned.m16n8k16.row.col.f32.f16.f16.f32 "
        "{%0,%1,%2,%3},{%4,%5,%6,%7},{%8,%9},{%0,%1,%2,%3};"
        : "+f"(d[0]),"+f"(d[1]),"+f"(d[2]),"+f"(d[3])
        : "r"(a[0]),"r"(a[1]),"r"(a[2]),"r"(a[3]),"r"(b[0]),"r"(b[1]));
}
__device__ __forceinline__ void cpa16(uint32_t dst, const void* src, bool ok){
    int sz = ok ? 16 : 0;
    asm volatile("cp.async.cg.shared.global [%0], [%1], 16, %2;" :: "r"(dst), "l"(src), "r"(sz) : "memory");
}
__device__ __forceinline__ float gelu_exact(float x){
    return 0.5f*x*(1.0f + erff(x*0.7071067811865476f));
}
__device__ __forceinline__ uint32_t f2h2(float a, float b){
    __half2 h = __floats2half2_rn(a, b);
    return *(uint32_t*)&h;
}

// ---------------- dummy (profiler alignment) ----------------
__global__ void k_dummy(){}

// ---------------- weight prep only ----------------
__global__ void __launch_bounds__(256) k_wprep(
    const float* __restrict__ qkvw,
    const float* __restrict__ c1w, const float* __restrict__ c2w,
    const float* __restrict__ bn1g, const float* __restrict__ bn1b,
    const float* __restrict__ bn1m, const float* __restrict__ bn1v,
    const float* __restrict__ bn2g, const float* __restrict__ bn2b,
    const float* __restrict__ bn2m, const float* __restrict__ bn2v,
    __half* __restrict__ wq, __half* __restrict__ wc1,
    __half* __restrict__ wc2, float* __restrict__ bn)
{
    int tid = threadIdx.x;
    int blk = blockIdx.x;
    if (blk < 48){
        int base = blk*4096 + tid;
        #pragma unroll
        for (int k = 0; k < 16; ++k){
            int i = base + k*256;
            wq[i] = __float2half(qkvw[i]);
        }
    } else if (blk < 336){
        int bb = blk - 48;
        const float* w = (bb < 144) ? c1w : c2w;
        __half* o = (bb < 144) ? wc1 : wc2;
        int base = (bb % 144)*4096 + tid;
        #pragma unroll
        for (int k = 0; k < 16; ++k){
            int i = base + k*256;
            int co = i / 2304, r = i % 2304, tap = r >> 8, ci = r & 255;
            o[i] = __float2half(w[(co*256 + ci)*9 + tap]);
        }
    } else {
        int i = tid;
        float s1 = bn1g[i]*rsqrtf(bn1v[i] + 1e-5f);
        bn[i] = s1; bn[256+i] = bn1b[i] - bn1m[i]*s1;
        float s2 = bn2g[i]*rsqrtf(bn2v[i] + 1e-5f);
        bn[512+i] = s2; bn[768+i] = bn2b[i] - bn2m[i]*s2;
    }
}

// ---------------- FUSED blockify + LN1 + qkv GEMM ----------------
// smem layout (bytes):
//   A       @0       : 128 rows x 264 halfs (528B)        = 67584
//   staging @67584   : fp32 [256 ch][132 w] (528B/row)    = 135168  } B0/B1 reuse
// total 202752.  B0 @67584, B1 @135168.
#define FST  67584
#define FB1  135168
#define FSMEM 202752

__device__ __forceinline__ void load_B_q(uint32_t sb, uint32_t off, int c,
    const __half* __restrict__ Bw, int tid)
{
    uint32_t bB = sb + off;
    const __half* Bb = Bw + (size_t)(c*128)*256;
    #pragma unroll
    for (int it = 0; it < 16; ++it){
        int idx = it*256 + tid;
        int n = idx >> 5, v = idx & 31;
        cpa16(bB + n*528 + v*16, Bb + n*256 + v*8, true);
    }
    asm volatile("cp.async.commit_group;" ::: "memory");
}

__global__ void __launch_bounds__(256) k_blk_qkv(
    const float* __restrict__ x,
    const float* __restrict__ gam, const float* __restrict__ bet,
    const __half* __restrict__ Bw,
    __half* __restrict__ g, __half* __restrict__ out)
{
    extern __shared__ char smem[];
    uint32_t sb = smem_u32(smem);
    int tid = threadIdx.x;
    int bm = blockIdx.x, b = bm >> 7, y = bm & 127;
    int warp = tid >> 5, lane = tid & 31;
    int hp = y & 15, gh = y >> 4;

    // ---- phase 1: x row -> fp32 staging [ch][132w] via cp.async (deep MLP) ----
    const float* xp = x + ((size_t)b*256)*16384 + y*128;
    #pragma unroll
    for (int it = 0; it < 32; ++it){
        int idx = it*256 + tid;          // 8192 chunks: ch(256) x v(32)
        int ch = idx >> 5, v = idx & 31;
        cpa16(sb + FST + ch*528 + v*16, xp + (size_t)ch*16384 + v*4, true);
    }
    asm volatile("cp.async.commit_group;" ::: "memory");
    asm volatile("cp.async.wait_group 0;" ::: "memory");
    __syncthreads();

    // ---- phase 2: LN per token -> g (gmem) + h (smem A region) ----
    {
        const float* s1f = (const float*)(smem + FST);
        float gm[8], bt[8];
        #pragma unroll
        for (int i = 0; i < 8; ++i){ gm[i] = gam[i*32 + lane]; bt[i] = bet[i*32 + lane]; }
        __half* hA = (__half*)smem;
        for (int t = warp; t < 128; t += 8){
            float v[8]; float sum = 0.f, sq = 0.f;
            #pragma unroll
            for (int i = 0; i < 8; ++i){
                v[i] = s1f[(i*32 + lane)*132 + t];
                sum += v[i]; sq += v[i]*v[i];
            }
            #pragma unroll
            for (int o = 16; o; o >>= 1){
                sum += __shfl_xor_sync(0xffffffffu, sum, o);
                sq  += __shfl_xor_sync(0xffffffffu, sq,  o);
            }
            float mean = sum*(1.f/256.f);
            float rstd = rsqrtf(sq*(1.f/256.f) - mean*mean + 1e-5f);
            int tok = ((b*16 + hp)*16 + (t & 15))*64 + gh*8 + (t >> 4);
            __half* gp = g + (size_t)tok*256;
            #pragma unroll
            for (int i = 0; i < 8; ++i){
                gp[i*32 + lane] = __float2half(v[i]);
                hA[t*264 + i*32 + lane] = __float2half((v[i]-mean)*rstd*gm[i] + bt[i]);
            }
        }
    }
    __syncthreads();   // staging dead from here; B0/B1 reuse it

    // ---- phase 3: stream B, GEMM (A resident) ----
    load_B_q(sb, FST, 0, Bw, tid);
    load_B_q(sb, FB1, 1, Bw, tid);

    int wm = warp >> 2, wn = warp & 3;     // 2x4 warps, warp tile 64x32
    uint32_t aRow = (wm*64 + (lane & 15))*528 + ((lane >> 4) & 1)*16;
    int mid = lane >> 3;
    uint32_t bRowP = (wn*32 + (mid >> 1)*8 + (lane & 7))*528 + (mid & 1)*16;
    int fr = lane >> 2, fc = lane & 3;

    #pragma unroll 1
    for (int c = 0; c < 6; ++c){
        if (c + 2 < 6) asm volatile("cp.async.wait_group 1;" ::: "memory");
        else           asm volatile("cp.async.wait_group 0;" ::: "memory");
        __syncthreads();
        float acc[4][4][4];
        #pragma unroll
        for (int i=0;i<4;i++)
          #pragma unroll
          for (int j=0;j<4;j++){ acc[i][j][0]=0.f; acc[i][j][1]=0.f; acc[i][j][2]=0.f; acc[i][j][3]=0.f; }
        uint32_t bB = sb + ((c & 1) ? FB1 : FST);
        #pragma unroll
        for (int ks = 0; ks < 16; ++ks){
            uint32_t af[4][4], bf[4][2];
            #pragma unroll
            for (int i = 0; i < 4; ++i)
                ldsm4(af[i], sb + aRow + i*16*528 + ks*32);
            #pragma unroll
            for (int jp = 0; jp < 2; ++jp){
                uint32_t r[4];
                ldsm4(r, bB + bRowP + jp*16*528 + ks*32);
                bf[2*jp][0] = r[0]; bf[2*jp][1] = r[1];
                bf[2*jp+1][0] = r[2]; bf[2*jp+1][1] = r[3];
            }
            #pragma unroll
            for (int i = 0; i < 4; ++i)
                #pragma unroll
                for (int j = 0; j < 4; ++j)
                    mma_f16(acc[i][j], af[i], bf[j]);
        }
        __syncthreads();
        if (c + 2 < 6) load_B_q(sb, ((c & 1) ? FB1 : FST), c + 2, Bw, tid);
        // epilogue: map tile row (x position) -> windowed token index
        #pragma unroll
        for (int i = 0; i < 4; ++i){
            int xr0 = wm*64 + i*16 + fr;
            int xr1 = xr0 + 8;
            int tok0 = ((b*16 + hp)*16 + (xr0 & 15))*64 + gh*8 + (xr0 >> 4);
            int tok1 = ((b*16 + hp)*16 + (xr1 & 15))*64 + gh*8 + (xr1 >> 4);
            #pragma unroll
            for (int j = 0; j < 4; ++j){
                int col = c*128 + wn*32 + j*8 + fc*2;
                *(__half2*)(out + (size_t)tok0*768 + col) = __floats2half2_rn(acc[i][j][0], acc[i][j][1]);
                *(__half2*)(out + (size_t)tok1*768 + col) = __floats2half2_rn(acc[i][j][2], acc[i][j][3]);
            }
        }
    }
}

// ---------------- implicit conv3x3 (128 thr, 2 CTAs/SM) ----------------
#define CSLOT 41120
#define CBOFF 10400
#define CSMEM 82240

__device__ __forceinline__ void load_stage_c(uint32_t sb, int slot, int s,
    const __half* __restrict__ A, const __half* __restrict__ Bw,
    int bm, int nbase, int tid)
{
    uint32_t aB = sb + slot*CSLOT;
    uint32_t bB = aB + CBOFF;
    int dyi = s >> 3, kq = s & 7;
    int y = bm & 127, b_img = bm >> 7;
    int yy = y + dyi - 1;
    bool yok = ((unsigned)yy < 128u);
    const __half* Ab = A + ((size_t)(b_img*128 + (yok ? yy : 0)))*128*256 + kq*32;
    #pragma unroll
    for (int it = 0; it < 5; ++it){
        int idx = it*128 + tid;
        if (idx < 520){
            int row = idx >> 2, v = idx & 3;     // row = x+1, 0..129
            int x = row - 1;
            bool ok = yok && ((unsigned)x < 128u);
            cpa16(aB + row*80 + v*16, Ab + (ok ? (x*256 + v*8) : v*8), ok);
        }
    }
    const __half* Bb = Bw + (size_t)nbase*2304 + dyi*3*256 + kq*32;
    #pragma unroll
    for (int it = 0; it < 12; ++it){
        int idx = it*128 + tid;
        int tap = idx >> 9, rem = idx & 511;
        int co = rem >> 2, v = rem & 3;
        cpa16(bB + tap*10240 + co*80 + v*16, Bb + (size_t)co*2304 + tap*256 + v*8, true);
    }
}

// EPI 1: bn+gelu -> fp16 NHWC.  EPI 3: bn+gelu+res -> fp32 NCHW (smem transpose).
template<int EPI>
__global__ void __launch_bounds__(128,2) k_conv_h(
    const __half* __restrict__ A, const __half* __restrict__ Bw,
    void* __restrict__ outv,
    const float* __restrict__ bnsc, const float* __restrict__ bnsh,
    const __half* __restrict__ res)
{
    extern __shared__ char smem[];
    uint32_t sb = smem_u32(smem);
    int tid = threadIdx.x;
    int bm = blockIdx.x;                 // b*128 + y
    int nbase = blockIdx.y << 7;
    const int NS = 24;

    int warp = tid >> 5, lane = tid & 31;
    int wm = warp >> 1, wn = warp & 1;   // 2x2 warps, warp tile 64x64

    float acc[4][8][4];
    #pragma unroll
    for (int i=0;i<4;i++)
      #pragma unroll
      for (int j=0;j<8;j++){ acc[i][j][0]=0.f; acc[i][j][1]=0.f; acc[i][j][2]=0.f; acc[i][j][3]=0.f; }

    load_stage_c(sb, 0, 0, A, Bw, bm, nbase, tid);
    asm volatile("cp.async.commit_group;" ::: "memory");
    load_stage_c(sb, 1, 1, A, Bw, bm, nbase, tid);
    asm volatile("cp.async.commit_group;" ::: "memory");

    uint32_t aRow = (wm*64 + (lane & 15))*80 + ((lane >> 4) & 1)*16;
    int mid = lane >> 3;  // matrix id for B pair loads
    uint32_t bRowP = (wn*64 + (mid >> 1)*8 + (lane & 7))*80 + (mid & 1)*16;

    #pragma unroll 1
    for (int s = 0; s < NS; ++s){
        if (s + 1 < NS) asm volatile("cp.async.wait_group 1;" ::: "memory");
        else            asm volatile("cp.async.wait_group 0;" ::: "memory");
        __syncthreads();
        uint32_t aB = sb + (s & 1)*CSLOT;
        uint32_t bB = aB + CBOFF;
        #pragma unroll
        for (int t = 0; t < 3; ++t){
            #pragma unroll
            for (int ks = 0; ks < 2; ++ks){
                uint32_t af[4][4], bf[8][2];
                #pragma unroll
                for (int i = 0; i < 4; ++i)
                    ldsm4(af[i], aB + aRow + t*80 + i*1280 + ks*32);
                #pragma unroll
                for (int jp = 0; jp < 4; ++jp){
                    uint32_t r[4];
                    ldsm4(r, bB + t*10240 + bRowP + jp*1280 + ks*32);
                    bf[2*jp][0] = r[0]; bf[2*jp][1] = r[1];
                    bf[2*jp+1][0] = r[2]; bf[2*jp+1][1] = r[3];
                }
                #pragma unroll
                for (int i = 0; i < 4; ++i)
                    #pragma unroll
                    for (int j = 0; j < 8; ++j)
                        mma_f16(acc[i][j], af[i], bf[j]);
            }
        }
        __syncthreads();
        if (s + 2 < NS){
            load_stage_c(sb, s & 1, s+2, A, Bw, bm, nbase, tid);
            asm volatile("cp.async.commit_group;" ::: "memory");
        }
    }

    int fr = lane >> 2, fc = lane & 3;
    if (EPI == 1){
        __half* out = (__half*)outv;
        #pragma unroll
        for (int i = 0; i < 4; ++i){
            #pragma unroll
            for (int j = 0; j < 8; ++j){
                size_t row = (size_t)bm*128 + wm*64 + i*16 + fr;
                int col = nbase + wn*64 + j*8 + fc*2;
                float sc0 = bnsc[col], sc1 = bnsc[col+1];
                float sh0 = bnsh[col], sh1 = bnsh[col+1];
                float v0 = gelu_exact(acc[i][j][0]*sc0 + sh0);
                float v1 = gelu_exact(acc[i][j][1]*sc1 + sh1);
                float v2 = gelu_exact(acc[i][j][2]*sc0 + sh0);
                float v3 = gelu_exact(acc[i][j][3]*sc1 + sh1);
                *(__half2*)(out + row*256 + col)     = __floats2half2_rn(v0, v1);
                *(__half2*)(out + (row+8)*256 + col) = __floats2half2_rn(v2, v3);
            }
        }
    } else {
        // EPI 3: bn+gelu+residual, transpose via smem, coalesced NCHW write
        float* st = (float*)smem;   // [128 c][132] floats = 67584 B
        #pragma unroll
        for (int i = 0; i < 4; ++i){
            #pragma unroll
            for (int j = 0; j < 8; ++j){
                int x = wm*64 + i*16 + fr;
                int c = wn*64 + j*8 + fc*2;
                int col = nbase + c;
                size_t row = (size_t)bm*128 + x;
                float sc0 = bnsc[col], sc1 = bnsc[col+1];
                float sh0 = bnsh[col], sh1 = bnsh[col+1];
                float v0 = gelu_exact(acc[i][j][0]*sc0 + sh0);
                float v1 = gelu_exact(acc[i][j][1]*sc1 + sh1);
                float v2 = gelu_exact(acc[i][j][2]*sc0 + sh0);
                float v3 = gelu_exact(acc[i][j][3]*sc1 + sh1);
                __half2 r0 = *(const __half2*)(res + row*256 + col);
                __half2 r1 = *(const __half2*)(res + (row+8)*256 + col);
                st[c*132 + x]         = v0 + __low2float(r0);
                st[(c+1)*132 + x]     = v1 + __high2float(r0);
                st[c*132 + x + 8]     = v2 + __low2float(r1);
                st[(c+1)*132 + x + 8] = v3 + __high2float(r1);
            }
        }
        __syncthreads();
        float* out = (float*)outv;
        int b_img = bm >> 7, y = bm & 127;
        #pragma unroll 1
        for (int it = 0; it < 32; ++it){
            int c = it*4 + warp;
            float4 v = *(const float4*)(st + c*132 + lane*4);
            *(float4*)(out + ((size_t)(b_img*256 + nbase + c)*128 + y)*128 + lane*4) = v;
        }
    }
}

// ---------------- fused tensor-core attention + LN2 + unblock (512 thr) ----------------
#define ATT_SMEM 194560
__global__ void __launch_bounds__(512) k_attn_ln(const __half* __restrict__ qkv,
    const float* __restrict__ rel_table,
    const __half* __restrict__ g,
    const float* __restrict__ gam, const float* __restrict__ bet,
    __half* __restrict__ u)
{
    extern __shared__ char smem[];
    uint32_t sb = smem_u32(smem);
    float* rqf = (float*)(smem + 122880);
    float* rkf = (float*)(smem + 124928);
    float* sof = (float*)(smem + 126976);
    int tid = threadIdx.x, warp = tid >> 5, lane = tid & 31;
    int head = warp >> 1, half = warp & 1;
    int win = blockIdx.x;

    const __half* src = qkv + (size_t)win*64*768;
    #pragma unroll
    for (int it = 0; it < 12; ++it){
        int c = it*512 + tid;           // 6144 16B chunks
        int n = c / 96, cc = c % 96;
        int col0 = cc*8;
        int part = col0 >> 8, rem = col0 & 255;
        int hh = rem >> 5, d0 = rem & 31;
        cpa16(sb + part*40960 + hh*5120 + n*80 + d0*2, src + n*768 + col0, true);
    }
    asm volatile("cp.async.commit_group;" ::: "memory");
    asm volatile("cp.async.wait_group 0;" ::: "memory");
    __syncthreads();

    {
        int id = tid;                    // head*64 + n
        const __half2* pq = (const __half2*)(smem + (id>>6)*5120 + (id&63)*80);
        const __half2* pk = (const __half2*)(smem + 40960 + (id>>6)*5120 + (id&63)*80);
        float ssq = 0.f, ssk = 0.f;
        #pragma unroll
        for (int d = 0; d < 16; ++d){
            float2 fq = __half22float2(pq[d]); ssq += fq.x*fq.x + fq.y*fq.y;
            float2 fk = __half22float2(pk[d]); ssk += fk.x*fk.x + fk.y*fk.y;
        }
        rqf[id] = rsqrtf(ssq);
        rkf[id] = rsqrtf(ssk);
    }
    __syncthreads();

    uint32_t sqh = sb + head*5120;
    uint32_t skh = sb + 40960 + head*5120;
    uint32_t svh = sb + 81920 + head*5120;
    const float* rqh = rqf + head*64;
    const float* rkh = rkf + head*64;
    int r0 = lane >> 2, cq = lane & 3;
    int qb = half*32;

    uint32_t af[2][2][4];
    #pragma unroll
    for (int i = 0; i < 2; ++i)
        #pragma unroll
        for (int kt = 0; kt < 2; ++kt)
            ldsm4(af[i][kt], sqh + (qb + i*16 + (lane & 15))*80 + (kt*16 + (lane >> 4)*8)*2);

    float s[2][8][4];
    #pragma unroll
    for (int i = 0; i < 2; ++i)
        #pragma unroll
        for (int j = 0; j < 8; ++j){ s[i][j][0]=0.f; s[i][j][1]=0.f; s[i][j][2]=0.f; s[i][j][3]=0.f; }

    #pragma unroll
    for (int j = 0; j < 8; ++j){
        uint32_t b0[2], b1[2];
        int l = lane & 15;
        uint32_t ka = skh + (j*8 + (l & 7))*80 + ((l >> 3)*8)*2;
        ldsm2(b0, ka);
        ldsm2(b1, ka + 32);
        #pragma unroll
        for (int i = 0; i < 2; ++i){
            mma_f16(s[i][j], af[i][0], b0);
            mma_f16(s[i][j], af[i][1], b1);
        }
    }

    #pragma unroll
    for (int i = 0; i < 2; ++i){
        int tok0 = qb + i*16 + r0;
        float rq0 = rqh[tok0]   * 0.17677669529663687f;
        float rq1 = rqh[tok0+8] * 0.17677669529663687f;
        int i1a = tok0 >> 3,     j1a = tok0 & 7;
        int i1b = (tok0+8) >> 3, j1b = (tok0+8) & 7;
        #pragma unroll
        for (int j = 0; j < 8; ++j){
            #pragma unroll
            for (int e = 0; e < 2; ++e){
                int col = j*8 + cq*2 + e;
                float rk = rkh[col];
                int i2 = col >> 3, j2 = col & 7;
                s[i][j][e]   = s[i][j][e]  *rq0*rk + rel_table[((i1a-i2+7)*15 + (j1a-j2+7))*8 + head];
                s[i][j][2+e] = s[i][j][2+e]*rq1*rk + rel_table[((i1b-i2+7)*15 + (j1b-j2+7))*8 + head];
            }
        }
    }

    #pragma unroll
    for (int i = 0; i < 2; ++i){
        #pragma unroll
        for (int p = 0; p < 2; ++p){
            float m = -1e30f;
            #pragma unroll
            for (int j = 0; j < 8; ++j){
                m = fmaxf(m, s[i][j][2*p]); m = fmaxf(m, s[i][j][2*p+1]);
            }
            m = fmaxf(m, __shfl_xor_sync(0xffffffffu, m, 1));
            m = fmaxf(m, __shfl_xor_sync(0xffffffffu, m, 2));
            float sum = 0.f;
            #pragma unroll
            for (int j = 0; j < 8; ++j){
                float e0 = __expf(s[i][j][2*p]   - m);
                float e1 = __expf(s[i][j][2*p+1] - m);
                s[i][j][2*p] = e0; s[i][j][2*p+1] = e1;
                sum += e0 + e1;
            }
            sum += __shfl_xor_sync(0xffffffffu, sum, 1);
            sum += __shfl_xor_sync(0xffffffffu, sum, 2);
            float inv = 1.0f/sum;
            #pragma unroll
            for (int j = 0; j < 8; ++j){ s[i][j][2*p] *= inv; s[i][j][2*p+1] *= inv; }
        }
    }

    float o[2][4][4];
    #pragma unroll
    for (int i = 0; i < 2; ++i)
        #pragma unroll
        for (int nt = 0; nt < 4; ++nt){ o[i][nt][0]=0.f; o[i][nt][1]=0.f; o[i][nt][2]=0.f; o[i][nt][3]=0.f; }

    #pragma unroll
    for (int kt = 0; kt < 4; ++kt){
        uint32_t pa[2][4];
        #pragma unroll
        for (int i = 0; i < 2; ++i){
            pa[i][0] = f2h2(s[i][2*kt][0],   s[i][2*kt][1]);
            pa[i][1] = f2h2(s[i][2*kt][2],   s[i][2*kt][3]);
            pa[i][2] = f2h2(s[i][2*kt+1][0], s[i][2*kt+1][1]);
            pa[i][3] = f2h2(s[i][2*kt+1][2], s[i][2*kt+1][3]);
        }
        #pragma unroll
        for (int nt = 0; nt < 4; ++nt){
            uint32_t bv[2];
            ldsm2t(bv, svh + (kt*16 + (lane & 15))*80 + nt*16);
            #pragma unroll
            for (int i = 0; i < 2; ++i)
                mma_f16(o[i][nt], pa[i], bv);
        }
    }

    #pragma unroll
    for (int i = 0; i < 2; ++i){
        int row = qb + i*16 + r0;
        #pragma unroll
        for (int nt = 0; nt < 4; ++nt){
            int col = head*32 + nt*8 + cq*2;
            *(float2*)&sof[row*264 + col]     = make_float2(o[i][nt][0], o[i][nt][1]);
            *(float2*)&sof[(row+8)*264 + col] = make_float2(o[i][nt][2], o[i][nt][3]);
        }
    }
    __syncthreads();

    int b = win >> 8, hp = (win >> 4) & 15, wp = win & 15;
    float4 gm0 = ((const float4*)gam)[lane*2], gm1 = ((const float4*)gam)[lane*2+1];
    float4 bt0 = ((const float4*)bet)[lane*2], bt1 = ((const float4*)bet)[lane*2+1];
    #pragma unroll 1
    for (int t = warp; t < 64; t += 16){
        const __half2* gp = (const __half2*)(g + ((size_t)win*64 + t)*256 + lane*8);
        float2 g0 = __half22float2(gp[0]), g1 = __half22float2(gp[1]);
        float2 g2 = __half22float2(gp[2]), g3 = __half22float2(gp[3]);
        const float* sp = &sof[t*264 + lane*8];
        float4 s0 = *(const float4*)sp;
        float4 s1 = *(const float4*)(sp + 4);
        float4 a0 = make_float4(g0.x+s0.x, g0.y+s0.y, g1.x+s0.z, g1.y+s0.w);
        float4 a1 = make_float4(g2.x+s1.x, g2.y+s1.y, g3.x+s1.z, g3.y+s1.w);
        float sum = a0.x+a0.y+a0.z+a0.w + a1.x+a1.y+a1.z+a1.w;
        float sq  = a0.x*a0.x+a0.y*a0.y+a0.z*a0.z+a0.w*a0.w
                  + a1.x*a1.x+a1.y*a1.y+a1.z*a1.z+a1.w*a1.w;
        #pragma unroll
        for (int o2 = 16; o2; o2 >>= 1){
            sum += __shfl_xor_sync(0xffffffffu, sum, o2);
            sq  += __shfl_xor_sync(0xffffffffu, sq,  o2);
        }
        float mean = sum*(1.f/256.f);
        float rstd = rsqrtf(sq*(1.f/256.f) - mean*mean + 1e-5f);
        uint4 pk;
        pk.x = f2h2((a0.x-mean)*rstd*gm0.x+bt0.x, (a0.y-mean)*rstd*gm0.y+bt0.y);
        pk.y = f2h2((a0.z-mean)*rstd*gm0.z+bt0.z, (a0.w-mean)*rstd*gm0.w+bt0.w);
        pk.z = f2h2((a1.x-mean)*rstd*gm1.x+bt1.x, (a1.y-mean)*rstd*gm1.y+bt1.y);
        pk.w = f2h2((a1.z-mean)*rstd*gm1.z+bt1.z, (a1.w-mean)*rstd*gm1.w+bt1.w);
        int gh = t >> 3, gw = t & 7;
        int y = gh*16 + hp, xx = gw*16 + wp;
        size_t st = ((size_t)b*128 + y)*128 + xx;
        *(uint4*)(u + st*256 + lane*8) = pk;
    }
}

// ---------------- launch ----------------
static float* symaddrf(const void* sym){
    void* p = nullptr; cudaGetSymbolAddress(&p, sym); return (float*)p;
}
static __half* symaddrh(const void* sym){
    void* p = nullptr; cudaGetSymbolAddress(&p, sym); return (__half*)p;
}

extern "C" void kernel_launch(void* const* d_in, const int* in_sizes, int n_in,
                              void* d_out, int out_size){
    const float* x      = (const float*)d_in[0];
    const float* ln1_g  = (const float*)d_in[1];
    const float* ln1_b  = (const float*)d_in[2];
    const float* qkv_w  = (const float*)d_in[3];
    const float* rel_t  = (const float*)d_in[4];
    const float* ln2_g  = (const float*)d_in[5];
    const float* ln2_b  = (const float*)d_in[6];
    const float* c1w    = (const float*)d_in[7];
    const float* bn1g   = (const float*)d_in[8];
    const float* bn1b   = (const float*)d_in[9];
    const float* bn1m   = (const float*)d_in[10];
    const float* bn1v   = (const float*)d_in[11];
    const float* c2w    = (const float*)d_in[12];
    const float* bn2g   = (const float*)d_in[13];
    const float* bn2b   = (const float*)d_in[14];
    const float* bn2m   = (const float*)d_in[15];
    const float* bn2v   = (const float*)d_in[16];
    float* out = (float*)d_out;

    __half* g    = symaddrh(d_g);
    __half* qkv  = symaddrh(d_qkv);
    __half* u16  = symaddrh(d_u16);
    __half* m116 = symaddrh(d_m116);
    __half* wq   = symaddrh(d_wq);
    __half* wc1  = symaddrh(d_wc1);
    __half* wc2  = symaddrh(d_wc2);
    float*  bn   = symaddrf(d_bn);
    float *sc1 = bn, *sh1 = bn+256, *sc2 = bn+512, *sh2 = bn+768;

    cudaFuncSetAttribute(k_blk_qkv,  cudaFuncAttributeMaxDynamicSharedMemorySize, FSMEM);
    cudaFuncSetAttribute(k_conv_h<1>,cudaFuncAttributeMaxDynamicSharedMemorySize, CSMEM);
    cudaFuncSetAttribute(k_conv_h<3>,cudaFuncAttributeMaxDynamicSharedMemorySize, CSMEM);
    cudaFuncSetAttribute(k_attn_ln,  cudaFuncAttributeMaxDynamicSharedMemorySize, ATT_SMEM);

    // 0: weight prep (wq must be ready before fused kernel)
    k_wprep<<<337, 256>>>(qkv_w, c1w, c2w, bn1g, bn1b, bn1m, bn1v,
                          bn2g, bn2b, bn2m, bn2v, wq, wc1, wc2, bn);
    // 1,2: profiler alignment (puts fused kernel at profiled index 3)
    k_dummy<<<1, 32>>>();
    k_dummy<<<1, 32>>>();
    // 3: FUSED blockify + LN1 + qkv GEMM (cp.async x load)   <- ncu profiles this
    k_blk_qkv<<<1024, 256, FSMEM>>>(x, ln1_g, ln1_b, wq, g, qkv);
    // 4: fused attention + LN2 + unblock (512 thr, 16 warps)
    k_attn_ln<<<2048, 512, ATT_SMEM>>>(qkv, rel_t, g, ln2_g, ln2_b, u16);
    // 5: conv1 + bn + gelu -> m1 fp16 NHWC
    k_conv_h<1><<<dim3(1024,2), 128, CSMEM>>>(u16, wc1, m116, sc1, sh1, nullptr);
    // 6: conv2 + bn + gelu + residual -> out fp32 NCHW
    k_conv_h<3><<<dim3(1024,2), 128, CSMEM>>>(m116, wc2, out, sc2, sh2, u16);
}